// round 16
// baseline (speedup 1.0000x reference)
#include <cuda_runtime.h>
#include <cuda_bf16.h>
#include <cstdint>
#include <math.h>

#define T 1024
#define H 1024
#define E 64
#define ISZ 512
#define TWO_I 1024
#define KTOP 6
#define NGRP 8
#define TKG 3
#define CAP 256
#define A_TOT (T*KTOP)
#define NSH_HALF 1024
#define NSH_2 2048

#define BKT 32
// A smem: two scalar bf16 planes (hi, lo), row pitch 40 bf16 = 20 words = 80B
#define PKW 20
#define A_PL 1280            // words per plane (64 rows * 20)
#define A_STG 2560           // words per stage (hi+lo)
#define A_STG_B 10240        // bytes per stage
#define A_PL_B 5120          // bytes per plane

// ---------------- scratch ----------------
__device__ float g_w[A_TOT];
__device__ int   g_eidx[A_TOT];
__device__ int   g_cnt[E];
__device__ int   g_off[E+1];
__device__ int   g_slot[A_TOT];
__device__ int   g_perm[A_TOT];
__device__ int   g_rowpos[A_TOT];
__device__ float g_actS[T*NSH_HALF];
__device__ float g_act[A_TOT*ISZ];
__device__ float g_y[A_TOT*H];

// ---------------- helpers ----------------
__device__ __forceinline__ uint32_t smem_u32(const void* p){
    uint32_t a;
    asm("{ .reg .u64 t; cvta.to.shared.u64 t, %1; cvt.u32.u64 %0, t; }" : "=r"(a) : "l"(p));
    return a;
}

__device__ __forceinline__ void mma_bf16(float* c, const uint32_t* a, const uint32_t* b){
    asm volatile(
        "mma.sync.aligned.m16n8k16.row.col.f32.bf16.bf16.f32 "
        "{%0,%1,%2,%3}, {%4,%5,%6,%7}, {%8,%9}, {%0,%1,%2,%3};"
        : "+f"(c[0]), "+f"(c[1]), "+f"(c[2]), "+f"(c[3])
        : "r"(a[0]), "r"(a[1]), "r"(a[2]), "r"(a[3]), "r"(b[0]), "r"(b[1]));
}

__device__ __forceinline__ void ldsm_x4(uint32_t& r0, uint32_t& r1, uint32_t& r2, uint32_t& r3, uint32_t addr){
    asm volatile("ldmatrix.sync.aligned.m8n8.x4.shared.b16 {%0,%1,%2,%3}, [%4];"
                 : "=r"(r0), "=r"(r1), "=r"(r2), "=r"(r3) : "r"(addr));
}
__device__ __forceinline__ void ldsm_x4_t(uint32_t& r0, uint32_t& r1, uint32_t& r2, uint32_t& r3, uint32_t addr){
    asm volatile("ldmatrix.sync.aligned.m8n8.x4.trans.shared.b16 {%0,%1,%2,%3}, [%4];"
                 : "=r"(r0), "=r"(r1), "=r"(r2), "=r"(r3) : "r"(addr));
}

// hi = truncate-to-bf16 of (x0,x1) packed; lo = rn-bf16 of remainders packed.
__device__ __forceinline__ void split_pair(float x0, float x1, uint32_t& h, uint32_t& l){
    uint32_t u0 = __float_as_uint(x0), u1 = __float_as_uint(x1);
    h = __byte_perm(u0, u1, 0x7632);
    float f0 = __uint_as_float(u0 & 0xFFFF0000u);
    float f1 = __uint_as_float(u1 & 0xFFFF0000u);
    __nv_bfloat162 lv = __floats2bfloat162_rn(x0 - f0, x1 - f1);
    l = *reinterpret_cast<uint32_t*>(&lv);
}

__device__ __forceinline__ float silu_mul(float g, float u){
    return (g / (1.f + expf(-g))) * u;
}

// ---------------- down-proj bf16x3 GEMM (BM=64, templated BN, 8 warps) ----------------
// mode 0: dense rows. mode 2: grouped rows = off[e]+m.
template<int BNv>
__global__ void __launch_bounds__(256, 3) mma_gemm(
    const float* __restrict__ A, const float* __restrict__ B, float* __restrict__ C,
    int Kd, int Nfull, long long BexpStride, int mode)
{
    constexpr int PNW  = (BNv + 8) / 2;     // words per B row per plane
    constexpr int B_PL = 32 * PNW;          // words per B plane
    constexpr int B_STG = 2 * B_PL;         // words per B stage (hi+lo)
    constexpr int CPB  = BNv / 16;          // B cols per loader thread
    constexpr int NF   = BNv / 32;          // n8 fragments per warp
    constexpr int NG   = NF / 2;            // ldsm n16 groups per warp
    extern __shared__ __align__(16) uint32_t smemu[];
    uint32_t* As = smemu;                   // [2][A_STG]
    uint32_t* Bs = smemu + 2*A_STG;         // [2][B_STG]
    const float** rowptr = (const float**)(smemu + 2*A_STG + 2*B_STG);

    int tid = threadIdx.x, wid = tid >> 5, lane = tid & 31;
    int n0 = blockIdx.x * BNv, m0 = blockIdx.y * 64;
    int cnt = 1 << 30, off = 0;
    const float* Bm = B;
    if (mode){
        int e = blockIdx.z;
        cnt = g_cnt[e]; if (cnt > CAP) cnt = CAP;
        if (m0 >= cnt) return;
        off = g_off[e];
        Bm = B + (size_t)e * (size_t)BexpStride;
    }
    if (tid < 64){
        int m = m0 + tid;
        const float* src;
        if (mode == 0)      src = A + (size_t)m * Kd;
        else if (m >= cnt)  src = A;
        else                src = A + (size_t)(off + m) * Kd;
        rowptr[tid] = src;
    }
    __syncthreads();

    // loader geometry
    int arow = tid >> 2, aoff = (tid & 3) * 8;
    int k2l = tid >> 4, colg = tid & 15;
    int cb = colg * CPB;
    const float* aptr = rowptr[arow] + aoff;
    const float* bptr0 = Bm + (size_t)(2*k2l) * Nfull + n0 + cb;
    const float* bptr1 = bptr0 + Nfull;

    const int NK = Kd / BKT;
    float4 pa0, pa1;
    float4 pb[CPB/4], qb[CPB/4];

    auto ldg = [&](int kt){
        size_t kc = (size_t)kt * BKT;
        pa0 = *(const float4*)(aptr + kc);
        pa1 = *(const float4*)(aptr + kc + 4);
        size_t bo = kc * Nfull;
        #pragma unroll
        for (int j = 0; j < CPB/4; j++){
            pb[j] = *(const float4*)(bptr0 + bo + 4*j);
            qb[j] = *(const float4*)(bptr1 + bo + 4*j);
        }
    };

    auto sts = [&](int s){
        // A: split into hi/lo planes
        uint32_t h[4], l[4];
        split_pair(pa0.x, pa0.y, h[0], l[0]);
        split_pair(pa0.z, pa0.w, h[1], l[1]);
        split_pair(pa1.x, pa1.y, h[2], l[2]);
        split_pair(pa1.z, pa1.w, h[3], l[3]);
        uint32_t* ad = As + s*A_STG + arow*PKW + (aoff >> 1);
        *(uint4*)ad          = make_uint4(h[0], h[1], h[2], h[3]);
        *(uint4*)(ad + A_PL) = make_uint4(l[0], l[1], l[2], l[3]);
        // B rows 2k2l, 2k2l+1
        uint32_t* bd = Bs + s*B_STG + (2*k2l)*PNW + (cb >> 1);
        uint32_t hb[CPB/2], lb[CPB/2];
        #pragma unroll
        for (int j = 0; j < CPB/4; j++){
            split_pair(pb[j].x, pb[j].y, hb[2*j],   lb[2*j]);
            split_pair(pb[j].z, pb[j].w, hb[2*j+1], lb[2*j+1]);
        }
        if (CPB == 8){
            *(uint4*)bd          = *(uint4*)hb;
            *(uint4*)(bd + B_PL) = *(uint4*)lb;
        } else {
            *(uint2*)bd          = *(uint2*)hb;
            *(uint2*)(bd + B_PL) = *(uint2*)lb;
        }
        #pragma unroll
        for (int j = 0; j < CPB/4; j++){
            split_pair(qb[j].x, qb[j].y, hb[2*j],   lb[2*j]);
            split_pair(qb[j].z, qb[j].w, hb[2*j+1], lb[2*j+1]);
        }
        bd += PNW;
        if (CPB == 8){
            *(uint4*)bd          = *(uint4*)hb;
            *(uint4*)(bd + B_PL) = *(uint4*)lb;
        } else {
            *(uint2*)bd          = *(uint2*)hb;
            *(uint2*)(bd + B_PL) = *(uint2*)lb;
        }
    };

    float acc[2][NF][4];
    #pragma unroll
    for (int i = 0; i < 2; i++)
        #pragma unroll
        for (int j = 0; j < NF; j++)
            #pragma unroll
            for (int v = 0; v < 4; v++) acc[i][j][v] = 0.f;

    int wm = (wid >> 2) * 32, wn = (wid & 3) * (NF*8);
    int lg = lane >> 2, lt = lane & 3;

    // ldmatrix lane addressing
    int lr = (lane & 7) + ((lane >> 3) & 1) * 8;
    int lk = (lane >> 4) * 8;
    uint32_t As_u = smem_u32(As), Bs_u = smem_u32(Bs);
    uint32_t aad[2];
    aad[0] = As_u + (uint32_t)(wm + lr) * 80u + (uint32_t)lk * 2u;
    aad[1] = aad[0] + 16u * 80u;
    uint32_t bad[NG];
    #pragma unroll
    for (int g = 0; g < NG; g++)
        bad[g] = Bs_u + (uint32_t)lr * (PNW*4u) + (uint32_t)(wn + g*16 + lk) * 2u;

    ldg(0);
    for (int kt = 0; kt < NK; kt++){
        int s = kt & 1;
        sts(s);
        __syncthreads();        // single barrier per iteration (safe w/ double buffer)
        if (kt + 1 < NK) ldg(kt + 1);

        uint32_t aS = s ? (uint32_t)A_STG_B : 0u;
        uint32_t bS = s ? (uint32_t)(B_STG*4) : 0u;
        #pragma unroll
        for (int ks = 0; ks < 2; ks++){
            uint32_t ah[2][4], al[2][4], bh[NF][2], bl[NF][2];
            #pragma unroll
            for (int mt = 0; mt < 2; mt++){
                uint32_t a0 = aad[mt] + aS + ks*32u;
                ldsm_x4(ah[mt][0], ah[mt][1], ah[mt][2], ah[mt][3], a0);
                ldsm_x4(al[mt][0], al[mt][1], al[mt][2], al[mt][3], a0 + A_PL_B);
            }
            #pragma unroll
            for (int g = 0; g < NG; g++){
                uint32_t b0 = bad[g] + bS + (uint32_t)(ks*16*PNW*4);
                ldsm_x4_t(bh[2*g][0], bh[2*g][1], bh[2*g+1][0], bh[2*g+1][1], b0);
                ldsm_x4_t(bl[2*g][0], bl[2*g][1], bl[2*g+1][0], bl[2*g+1][1], b0 + B_PL*4);
            }
            #pragma unroll
            for (int mt = 0; mt < 2; mt++)
                #pragma unroll
                for (int nt = 0; nt < NF; nt++){
                    mma_bf16(acc[mt][nt], ah[mt], bh[nt]);
                    mma_bf16(acc[mt][nt], ah[mt], bl[nt]);
                    mma_bf16(acc[mt][nt], al[mt], bh[nt]);
                }
        }
    }

    #pragma unroll
    for (int mt = 0; mt < 2; mt++){
        int r0 = m0 + wm + mt*16 + lg;
        int r1 = r0 + 8;
        bool v0 = (mode == 0) || (r0 < cnt);
        bool v1 = (mode == 0) || (r1 < cnt);
        size_t cr0 = (size_t)((mode == 0) ? r0 : off + r0) * Nfull;
        size_t cr1 = (size_t)((mode == 0) ? r1 : off + r1) * Nfull;
        #pragma unroll
        for (int nt = 0; nt < NF; nt++){
            int col = n0 + wn + nt*8 + 2*lt;
            if (v0) *(float2*)(C + cr0 + col) = make_float2(acc[mt][nt][0], acc[mt][nt][1]);
            if (v1) *(float2*)(C + cr1 + col) = make_float2(acc[mt][nt][2], acc[mt][nt][3]);
        }
    }
}

// ---------------- fused gate_up + silu GEMM (BM=64, two 64-wide halves, 8 warps) ------
#define GPNW 36
#define GB_PL (32*GPNW)         // 1152 words per plane
#define GB_STG (4*GB_PL)        // hi_g, lo_g, hi_u, lo_u
__global__ void __launch_bounds__(256, 3) mma_gemm_silu(
    const float* __restrict__ A, const float* __restrict__ B, float* __restrict__ Cact,
    int Kd, int Nfull, long long BexpStride, int mode)
{
    const int halfN = Nfull >> 1;
    extern __shared__ __align__(16) uint32_t smemu[];
    uint32_t* As = smemu;                   // [2][A_STG]
    uint32_t* Bs = smemu + 2*A_STG;         // [2][GB_STG]
    const float** rowptr = (const float**)(smemu + 2*A_STG + 2*GB_STG);

    int tid = threadIdx.x, wid = tid >> 5, lane = tid & 31;
    int n0 = blockIdx.x * 64, m0 = blockIdx.y * 64;
    int cnt = 1 << 30, off = 0;
    const float* Bm = B;
    if (mode){
        int e = blockIdx.z;
        cnt = g_cnt[e]; if (cnt > CAP) cnt = CAP;
        if (m0 >= cnt) return;
        off = g_off[e];
        Bm = B + (size_t)e * (size_t)BexpStride;
    }
    if (tid < 64){
        int m = m0 + tid;
        const float* src;
        if (mode == 0)      src = A + (size_t)m * Kd;
        else if (m >= cnt)  src = A;
        else                src = A + (size_t)(g_perm[off + m] / KTOP) * Kd;
        rowptr[tid] = src;
    }
    __syncthreads();

    int arow = tid >> 2, aoff = (tid & 3) * 8;
    int k2l = tid >> 4, colg = tid & 15;
    int cb = colg * 4;
    const float* aptr = rowptr[arow] + aoff;
    const float* bg0 = Bm + (size_t)(2*k2l) * Nfull + n0 + cb;
    const float* bg1 = bg0 + Nfull;

    const int NK = Kd / BKT;
    float4 pa0, pa1, pg0, pg1, pu0, pu1;

    auto ldg = [&](int kt){
        size_t kc = (size_t)kt * BKT;
        pa0 = *(const float4*)(aptr + kc);
        pa1 = *(const float4*)(aptr + kc + 4);
        size_t bo = kc * Nfull;
        pg0 = *(const float4*)(bg0 + bo);
        pg1 = *(const float4*)(bg1 + bo);
        pu0 = *(const float4*)(bg0 + bo + halfN);
        pu1 = *(const float4*)(bg1 + bo + halfN);
    };

    auto sts = [&](int s){
        uint32_t h[4], l[4];
        split_pair(pa0.x, pa0.y, h[0], l[0]);
        split_pair(pa0.z, pa0.w, h[1], l[1]);
        split_pair(pa1.x, pa1.y, h[2], l[2]);
        split_pair(pa1.z, pa1.w, h[3], l[3]);
        uint32_t* ad = As + s*A_STG + arow*PKW + (aoff >> 1);
        *(uint4*)ad          = make_uint4(h[0], h[1], h[2], h[3]);
        *(uint4*)(ad + A_PL) = make_uint4(l[0], l[1], l[2], l[3]);

        uint32_t h0, h1, l0, l1;
        uint32_t* bd = Bs + s*GB_STG + (2*k2l)*GPNW + (cb >> 1);
        split_pair(pg0.x, pg0.y, h0, l0); split_pair(pg0.z, pg0.w, h1, l1);
        *(uint2*)bd           = make_uint2(h0, h1);
        *(uint2*)(bd + GB_PL) = make_uint2(l0, l1);
        split_pair(pg1.x, pg1.y, h0, l0); split_pair(pg1.z, pg1.w, h1, l1);
        *(uint2*)(bd + GPNW)          = make_uint2(h0, h1);
        *(uint2*)(bd + GPNW + GB_PL)  = make_uint2(l0, l1);
        bd += 2*GB_PL;
        split_pair(pu0.x, pu0.y, h0, l0); split_pair(pu0.z, pu0.w, h1, l1);
        *(uint2*)bd           = make_uint2(h0, h1);
        *(uint2*)(bd + GB_PL) = make_uint2(l0, l1);
        split_pair(pu1.x, pu1.y, h0, l0); split_pair(pu1.z, pu1.w, h1, l1);
        *(uint2*)(bd + GPNW)          = make_uint2(h0, h1);
        *(uint2*)(bd + GPNW + GB_PL)  = make_uint2(l0, l1);
    };

    float acc[2][2][2][4];   // [m][half][nt][v]
    #pragma unroll
    for (int i = 0; i < 2; i++)
        #pragma unroll
        for (int hh = 0; hh < 2; hh++)
            #pragma unroll
            for (int j = 0; j < 2; j++)
                #pragma unroll
                for (int v = 0; v < 4; v++) acc[i][hh][j][v] = 0.f;

    int wm = (wid >> 2) * 32, wn = (wid & 3) * 16;
    int lg = lane >> 2, lt = lane & 3;

    int lr = (lane & 7) + ((lane >> 3) & 1) * 8;
    int lk = (lane >> 4) * 8;
    uint32_t As_u = smem_u32(As), Bs_u = smem_u32(Bs);
    uint32_t aad[2];
    aad[0] = As_u + (uint32_t)(wm + lr) * 80u + (uint32_t)lk * 2u;
    aad[1] = aad[0] + 16u * 80u;
    uint32_t bad[2];
    #pragma unroll
    for (int hh = 0; hh < 2; hh++)
        bad[hh] = Bs_u + (uint32_t)(hh * 2 * GB_PL * 4) + (uint32_t)lr * (GPNW*4u) + (uint32_t)(wn + lk) * 2u;

    ldg(0);
    for (int kt = 0; kt < NK; kt++){
        int s = kt & 1;
        sts(s);
        __syncthreads();        // single barrier per iteration
        if (kt + 1 < NK) ldg(kt + 1);

        uint32_t aS = s ? (uint32_t)A_STG_B : 0u;
        uint32_t bS = s ? (uint32_t)(GB_STG*4) : 0u;
        #pragma unroll
        for (int ks = 0; ks < 2; ks++){
            uint32_t ah[2][4], al[2][4], bh[2][2][2], bl[2][2][2];
            #pragma unroll
            for (int mt = 0; mt < 2; mt++){
                uint32_t a0 = aad[mt] + aS + ks*32u;
                ldsm_x4(ah[mt][0], ah[mt][1], ah[mt][2], ah[mt][3], a0);
                ldsm_x4(al[mt][0], al[mt][1], al[mt][2], al[mt][3], a0 + A_PL_B);
            }
            #pragma unroll
            for (int hh = 0; hh < 2; hh++){
                uint32_t b0 = bad[hh] + bS + (uint32_t)(ks*16*GPNW*4);
                ldsm_x4_t(bh[hh][0][0], bh[hh][0][1], bh[hh][1][0], bh[hh][1][1], b0);
                ldsm_x4_t(bl[hh][0][0], bl[hh][0][1], bl[hh][1][0], bl[hh][1][1], b0 + GB_PL*4);
            }
            #pragma unroll
            for (int mt = 0; mt < 2; mt++)
                #pragma unroll
                for (int hh = 0; hh < 2; hh++)
                    #pragma unroll
                    for (int nt = 0; nt < 2; nt++){
                        mma_bf16(acc[mt][hh][nt], ah[mt], bh[hh][nt]);
                        mma_bf16(acc[mt][hh][nt], ah[mt], bl[hh][nt]);
                        mma_bf16(acc[mt][hh][nt], al[mt], bh[hh][nt]);
                    }
        }
    }

    #pragma unroll
    for (int mt = 0; mt < 2; mt++){
        int r0 = m0 + wm + mt*16 + lg;
        int r1 = r0 + 8;
        bool v0 = (mode == 0) || (r0 < cnt);
        bool v1 = (mode == 0) || (r1 < cnt);
        size_t cr0 = (size_t)((mode == 0) ? r0 : off + r0) * halfN;
        size_t cr1 = (size_t)((mode == 0) ? r1 : off + r1) * halfN;
        #pragma unroll
        for (int nt = 0; nt < 2; nt++){
            int col = n0 + wn + nt*8 + 2*lt;
            if (v0){
                float2 o = make_float2(silu_mul(acc[mt][0][nt][0], acc[mt][1][nt][0]),
                                       silu_mul(acc[mt][0][nt][1], acc[mt][1][nt][1]));
                *(float2*)(Cact + cr0 + col) = o;
            }
            if (v1){
                float2 o = make_float2(silu_mul(acc[mt][0][nt][2], acc[mt][1][nt][2]),
                                       silu_mul(acc[mt][0][nt][3], acc[mt][1][nt][3]));
                *(float2*)(Cact + cr1 + col) = o;
            }
        }
    }
}

// ---------------- router: 8 tokens per block ----------------
__global__ __launch_bounds__(256) void router_topk(
    const float* __restrict__ x, const float* __restrict__ gw, const float* __restrict__ bias)
{
    __shared__ float xs[8][H];
    __shared__ float part[4][8][64];
    __shared__ float sc[8][64], sbb[8][64];
    int t0 = blockIdx.x * 8;
    for (int i = threadIdx.x; i < 8 * (H/4); i += 256){
        int tk = i / (H/4), j = i % (H/4);
        ((float4*)xs[tk])[j] = ((const float4*)(x + (size_t)(t0 + tk) * H))[j];
    }
    __syncthreads();
    int c = threadIdx.x >> 6, e = threadIdx.x & 63;
    float acc[8];
    #pragma unroll
    for (int tk = 0; tk < 8; tk++) acc[tk] = 0.f;
    const float* w = gw + (size_t)c * 256 * 64 + e;
    for (int h = 0; h < 256; h++){
        float wv = w[(size_t)h * 64];
        float* xcol = &xs[0][c * 256 + h];
        #pragma unroll
        for (int tk = 0; tk < 8; tk++) acc[tk] += xcol[tk * H] * wv;
    }
    #pragma unroll
    for (int tk = 0; tk < 8; tk++) part[c][tk][e] = acc[tk];
    __syncthreads();
    for (int i = threadIdx.x; i < 512; i += 256){
        int tk = i >> 6, ee = i & 63;
        float l = part[0][tk][ee] + part[1][tk][ee] + part[2][tk][ee] + part[3][tk][ee];
        float s = 1.f / (1.f + expf(-l));
        sc[tk][ee] = s; sbb[tk][ee] = s + bias[ee];
    }
    __syncthreads();
    if (threadIdx.x < 8){
        int tk = threadIdx.x;
        int t = t0 + tk;
        float gs[NGRP];
        #pragma unroll
        for (int g = 0; g < NGRP; g++){
            float m1 = -1e30f, m2 = -1e30f;
            #pragma unroll
            for (int j = 0; j < 8; j++){
                float v = sbb[tk][g * 8 + j];
                if (v > m1){ m2 = m1; m1 = v; } else if (v > m2){ m2 = v; }
            }
            gs[g] = m1 + m2;
        }
        unsigned gsel = 0;
        #pragma unroll
        for (int it = 0; it < TKG; it++){
            float best = -1e30f; int bi = 0;
            for (int g = 0; g < NGRP; g++)
                if (!((gsel >> g) & 1) && gs[g] > best){ best = gs[g]; bi = g; }
            gsel |= 1u << bi;
        }
        unsigned long long used = 0; float wsum = 0.f;
        float wk[KTOP]; int ek[KTOP];
        #pragma unroll
        for (int it = 0; it < KTOP; it++){
            float best = -1e30f; int bi = 0;
            for (int ee = 0; ee < 64; ee++){
                if (((gsel >> (ee >> 3)) & 1) && !((used >> ee) & 1) && sbb[tk][ee] > best){
                    best = sbb[tk][ee]; bi = ee;
                }
            }
            used |= 1ull << bi;
            ek[it] = bi; wk[it] = sc[tk][bi]; wsum += sc[tk][bi];
        }
        float inv = 1.f / wsum;
        #pragma unroll
        for (int k = 0; k < KTOP; k++){
            g_eidx[t * KTOP + k] = ek[k];
            g_w[t * KTOP + k] = wk[k] * inv;
        }
    }
}

// ---------------- fused dispatch (scan via shared memory) ----------------
__global__ __launch_bounds__(1024) void dispatch_k()
{
    __shared__ int scnt[E];
    int tid = threadIdx.x;
    if (tid < E) g_cnt[tid] = 0;
    __syncthreads();
    for (int a = tid; a < A_TOT; a += 1024)
        g_slot[a] = atomicAdd(&g_cnt[g_eidx[a]], 1);
    __syncthreads();
    if (tid < E){
        int c = g_cnt[tid];
        scnt[tid] = (c > CAP) ? CAP : c;
    }
    __syncthreads();
    if (tid == 0){
        int s = 0;
        #pragma unroll
        for (int e = 0; e < E; e++){ g_off[e] = s; s += scnt[e]; }
        g_off[E] = s;
    }
    __syncthreads();
    for (int a = tid; a < A_TOT; a += 1024){
        int e = g_eidx[a], sl = g_slot[a];
        if (sl < CAP){ int r = g_off[e] + sl; g_perm[r] = a; g_rowpos[a] = r; }
        else g_rowpos[a] = -1;
    }
}

// ---------------- combine ----------------
__global__ __launch_bounds__(256) void combine_k(float* __restrict__ out)
{
    int t = blockIdx.x;
    int h0 = threadIdx.x * 4;
    float4 acc = *(float4*)&out[(size_t)t * H + h0];
    #pragma unroll
    for (int k = 0; k < KTOP; k++){
        int a = t * KTOP + k;
        int r = g_rowpos[a];
        if (r >= 0){
            float w = 2.5f * g_w[a];
            float4 y = *(const float4*)&g_y[(size_t)r * H + h0];
            acc.x += w * y.x; acc.y += w * y.y; acc.z += w * y.z; acc.w += w * y.w;
        }
    }
    *(float4*)&out[(size_t)t * H + h0] = acc;
}

// ---------------- launch ----------------
extern "C" void kernel_launch(void* const* d_in, const int* in_sizes, int n_in,
                              void* d_out, int out_size)
{
    const float* x      = (const float*)d_in[0];
    const float* gate_w = (const float*)d_in[1];
    const float* e_bias = (const float*)d_in[2];
    const float* w_gu   = (const float*)d_in[3];
    const float* w_dn   = (const float*)d_in[4];
    const float* ws_gu  = (const float*)d_in[5];
    const float* ws_dn  = (const float*)d_in[6];
    float* out = (float*)d_out;

    float *p_actS, *p_act, *p_y;
    cudaGetSymbolAddress((void**)&p_actS, g_actS);
    cudaGetSymbolAddress((void**)&p_act,  g_act);
    cudaGetSymbolAddress((void**)&p_y,    g_y);

    const int SMEM_DN128 = (2*A_STG + 2*2*(32*68))*4 + 64*8;
    const int SMEM_DN64  = (2*A_STG + 2*2*(32*36))*4 + 64*8;
    const int SMEM_GU    = (2*A_STG + 2*GB_STG)*4 + 64*8;
    cudaFuncSetAttribute(mma_gemm<128>, cudaFuncAttributeMaxDynamicSharedMemorySize, SMEM_DN128);
    cudaFuncSetAttribute(mma_gemm<64>,  cudaFuncAttributeMaxDynamicSharedMemorySize, SMEM_DN64);
    cudaFuncSetAttribute(mma_gemm_silu, cudaFuncAttributeMaxDynamicSharedMemorySize, SMEM_GU);

    // fork a second stream for the shared-expert chain (independent of routing)
    cudaStream_t s1;
    cudaStreamCreateWithFlags(&s1, cudaStreamNonBlocking);
    cudaEvent_t evFork, evJoin;
    cudaEventCreateWithFlags(&evFork, cudaEventDisableTiming);
    cudaEventCreateWithFlags(&evJoin, cudaEventDisableTiming);
    cudaEventRecord(evFork, 0);
    cudaStreamWaitEvent(s1, evFork, 0);

    // stream s1: shared experts (gu+silu -> actS, down -> out)
    mma_gemm_silu<<<dim3(NSH_HALF / 64, T / 64, 1), 256, SMEM_GU, s1>>>(
        x, ws_gu, p_actS, H, NSH_2, 0, 0);
    mma_gemm<64><<<dim3(H / 64, T / 64, 1), 256, SMEM_DN64, s1>>>(
        p_actS, ws_dn, out, NSH_HALF, H, 0, 0);
    cudaEventRecord(evJoin, s1);

    // stream 0: router + dispatch + routed experts
    router_topk<<<T/8, 256>>>(x, gate_w, e_bias);
    dispatch_k<<<1, 1024>>>();
    mma_gemm_silu<<<dim3(ISZ / 64, CAP / 64, E), 256, SMEM_GU>>>(
        x, w_gu, p_act, H, TWO_I, (long long)H * TWO_I, 1);
    mma_gemm<128><<<dim3(H / 128, CAP / 64, E), 256, SMEM_DN128>>>(
        p_act, w_dn, p_y, ISZ, H, (long long)ISZ * H, 2);

    // join: combine (reads out written by dn_shared on s1, and g_y from stream 0)
    cudaStreamWaitEvent(0, evJoin, 0);
    combine_k<<<T, 256>>>(out);

    cudaEventDestroy(evFork);
    cudaEventDestroy(evJoin);
    cudaStreamDestroy(s1);
}

// round 17
// speedup vs baseline: 1.3786x; 1.3786x over previous
#include <cuda_runtime.h>
#include <cuda_bf16.h>
#include <cstdint>
#include <math.h>

#define T 1024
#define H 1024
#define E 64
#define ISZ 512
#define TWO_I 1024
#define KTOP 6
#define NGRP 8
#define TKG 3
#define CAP 256
#define A_TOT (T*KTOP)
#define NSH_HALF 1024
#define NSH_2 2048

#define BKT 32
// A smem: two scalar bf16 planes (hi, lo), row pitch 40 bf16 = 20 words = 80B
#define PKW 20
#define A_PL 1280            // words per plane (64 rows * 20)
#define A_STG 2560           // words per stage (hi+lo)
#define A_STG_B 10240        // bytes per stage
#define A_PL_B 5120          // bytes per plane

// ---------------- scratch ----------------
__device__ float g_w[A_TOT];
__device__ int   g_eidx[A_TOT];
__device__ int   g_cnt[E];
__device__ int   g_off[E+1];
__device__ int   g_perm[A_TOT];
__device__ int   g_rowpos[A_TOT];
__device__ float g_actS[T*NSH_HALF];
__device__ float g_act[A_TOT*ISZ];
__device__ float g_y[A_TOT*H];

// ---------------- helpers ----------------
__device__ __forceinline__ uint32_t smem_u32(const void* p){
    uint32_t a;
    asm("{ .reg .u64 t; cvta.to.shared.u64 t, %1; cvt.u32.u64 %0, t; }" : "=r"(a) : "l"(p));
    return a;
}

__device__ __forceinline__ void mma_bf16(float* c, const uint32_t* a, const uint32_t* b){
    asm volatile(
        "mma.sync.aligned.m16n8k16.row.col.f32.bf16.bf16.f32 "
        "{%0,%1,%2,%3}, {%4,%5,%6,%7}, {%8,%9}, {%0,%1,%2,%3};"
        : "+f"(c[0]), "+f"(c[1]), "+f"(c[2]), "+f"(c[3])
        : "r"(a[0]), "r"(a[1]), "r"(a[2]), "r"(a[3]), "r"(b[0]), "r"(b[1]));
}

__device__ __forceinline__ void ldsm_x4(uint32_t& r0, uint32_t& r1, uint32_t& r2, uint32_t& r3, uint32_t addr){
    asm volatile("ldmatrix.sync.aligned.m8n8.x4.shared.b16 {%0,%1,%2,%3}, [%4];"
                 : "=r"(r0), "=r"(r1), "=r"(r2), "=r"(r3) : "r"(addr));
}
__device__ __forceinline__ void ldsm_x4_t(uint32_t& r0, uint32_t& r1, uint32_t& r2, uint32_t& r3, uint32_t addr){
    asm volatile("ldmatrix.sync.aligned.m8n8.x4.trans.shared.b16 {%0,%1,%2,%3}, [%4];"
                 : "=r"(r0), "=r"(r1), "=r"(r2), "=r"(r3) : "r"(addr));
}

// hi = truncate-to-bf16 of (x0,x1) packed; lo = rn-bf16 of remainders packed.
__device__ __forceinline__ void split_pair(float x0, float x1, uint32_t& h, uint32_t& l){
    uint32_t u0 = __float_as_uint(x0), u1 = __float_as_uint(x1);
    h = __byte_perm(u0, u1, 0x7632);
    float f0 = __uint_as_float(u0 & 0xFFFF0000u);
    float f1 = __uint_as_float(u1 & 0xFFFF0000u);
    __nv_bfloat162 lv = __floats2bfloat162_rn(x0 - f0, x1 - f1);
    l = *reinterpret_cast<uint32_t*>(&lv);
}

__device__ __forceinline__ float silu_mul(float g, float u){
    return (g / (1.f + expf(-g))) * u;
}

// ---------------- down-proj bf16x3 GEMM (BM=64, templated BN, 8 warps) ----------------
// mode 0: dense rows. mode 2: grouped rows = off[e]+m.
template<int BNv>
__global__ void __launch_bounds__(256, 2) mma_gemm(
    const float* __restrict__ A, const float* __restrict__ B, float* __restrict__ C,
    int Kd, int Nfull, long long BexpStride, int mode)
{
    constexpr int PNW  = (BNv + 8) / 2;     // words per B row per plane
    constexpr int B_PL = 32 * PNW;          // words per B plane
    constexpr int B_STG = 2 * B_PL;         // words per B stage (hi+lo)
    constexpr int CPB  = BNv / 16;          // B cols per loader thread
    constexpr int NF   = BNv / 32;          // n8 fragments per warp
    constexpr int NG   = NF / 2;            // ldsm n16 groups per warp
    extern __shared__ __align__(16) uint32_t smemu[];
    uint32_t* As = smemu;                   // [2][A_STG]
    uint32_t* Bs = smemu + 2*A_STG;         // [2][B_STG]
    const float** rowptr = (const float**)(smemu + 2*A_STG + 2*B_STG);

    int tid = threadIdx.x, wid = tid >> 5, lane = tid & 31;
    int n0 = blockIdx.x * BNv, m0 = blockIdx.y * 64;
    int cnt = 1 << 30, off = 0;
    const float* Bm = B;
    if (mode){
        int e = blockIdx.z;
        cnt = g_cnt[e]; if (cnt > CAP) cnt = CAP;
        if (m0 >= cnt) return;
        off = g_off[e];
        Bm = B + (size_t)e * (size_t)BexpStride;
    }
    if (tid < 64){
        int m = m0 + tid;
        const float* src;
        if (mode == 0)      src = A + (size_t)m * Kd;
        else if (m >= cnt)  src = A;
        else                src = A + (size_t)(off + m) * Kd;
        rowptr[tid] = src;
    }
    __syncthreads();

    // loader geometry
    int arow = tid >> 2, aoff = (tid & 3) * 8;
    int k2l = tid >> 4, colg = tid & 15;
    int cb = colg * CPB;
    const float* aptr = rowptr[arow] + aoff;
    const float* bptr0 = Bm + (size_t)(2*k2l) * Nfull + n0 + cb;
    const float* bptr1 = bptr0 + Nfull;

    const int NK = Kd / BKT;
    float4 pa0, pa1;
    float4 pb[CPB/4], qb[CPB/4];

    auto ldg = [&](int kt){
        size_t kc = (size_t)kt * BKT;
        pa0 = *(const float4*)(aptr + kc);
        pa1 = *(const float4*)(aptr + kc + 4);
        size_t bo = kc * Nfull;
        #pragma unroll
        for (int j = 0; j < CPB/4; j++){
            pb[j] = *(const float4*)(bptr0 + bo + 4*j);
            qb[j] = *(const float4*)(bptr1 + bo + 4*j);
        }
    };

    auto sts = [&](int s){
        // A: split into hi/lo planes
        uint32_t h[4], l[4];
        split_pair(pa0.x, pa0.y, h[0], l[0]);
        split_pair(pa0.z, pa0.w, h[1], l[1]);
        split_pair(pa1.x, pa1.y, h[2], l[2]);
        split_pair(pa1.z, pa1.w, h[3], l[3]);
        uint32_t* ad = As + s*A_STG + arow*PKW + (aoff >> 1);
        *(uint4*)ad          = make_uint4(h[0], h[1], h[2], h[3]);
        *(uint4*)(ad + A_PL) = make_uint4(l[0], l[1], l[2], l[3]);
        // B rows 2k2l, 2k2l+1
        uint32_t* bd = Bs + s*B_STG + (2*k2l)*PNW + (cb >> 1);
        uint32_t hb[CPB/2], lb[CPB/2];
        #pragma unroll
        for (int j = 0; j < CPB/4; j++){
            split_pair(pb[j].x, pb[j].y, hb[2*j],   lb[2*j]);
            split_pair(pb[j].z, pb[j].w, hb[2*j+1], lb[2*j+1]);
        }
        if (CPB == 8){
            *(uint4*)bd          = *(uint4*)hb;
            *(uint4*)(bd + B_PL) = *(uint4*)lb;
        } else {
            *(uint2*)bd          = *(uint2*)hb;
            *(uint2*)(bd + B_PL) = *(uint2*)lb;
        }
        #pragma unroll
        for (int j = 0; j < CPB/4; j++){
            split_pair(qb[j].x, qb[j].y, hb[2*j],   lb[2*j]);
            split_pair(qb[j].z, qb[j].w, hb[2*j+1], lb[2*j+1]);
        }
        bd += PNW;
        if (CPB == 8){
            *(uint4*)bd          = *(uint4*)hb;
            *(uint4*)(bd + B_PL) = *(uint4*)lb;
        } else {
            *(uint2*)bd          = *(uint2*)hb;
            *(uint2*)(bd + B_PL) = *(uint2*)lb;
        }
    };

    float acc[2][NF][4];
    #pragma unroll
    for (int i = 0; i < 2; i++)
        #pragma unroll
        for (int j = 0; j < NF; j++)
            #pragma unroll
            for (int v = 0; v < 4; v++) acc[i][j][v] = 0.f;

    int wm = (wid >> 2) * 32, wn = (wid & 3) * (NF*8);
    int lg = lane >> 2, lt = lane & 3;

    // ldmatrix lane addressing
    int lr = (lane & 7) + ((lane >> 3) & 1) * 8;
    int lk = (lane >> 4) * 8;
    uint32_t As_u = smem_u32(As), Bs_u = smem_u32(Bs);
    uint32_t aad[2];
    aad[0] = As_u + (uint32_t)(wm + lr) * 80u + (uint32_t)lk * 2u;
    aad[1] = aad[0] + 16u * 80u;
    uint32_t bad[NG];
    #pragma unroll
    for (int g = 0; g < NG; g++)
        bad[g] = Bs_u + (uint32_t)lr * (PNW*4u) + (uint32_t)(wn + g*16 + lk) * 2u;

    ldg(0);
    for (int kt = 0; kt < NK; kt++){
        int s = kt & 1;
        sts(s);
        __syncthreads();        // single barrier per iteration (safe w/ double buffer)
        if (kt + 1 < NK) ldg(kt + 1);

        uint32_t aS = s ? (uint32_t)A_STG_B : 0u;
        uint32_t bS = s ? (uint32_t)(B_STG*4) : 0u;
        #pragma unroll
        for (int ks = 0; ks < 2; ks++){
            uint32_t ah[2][4], al[2][4], bh[NF][2], bl[NF][2];
            #pragma unroll
            for (int mt = 0; mt < 2; mt++){
                uint32_t a0 = aad[mt] + aS + ks*32u;
                ldsm_x4(ah[mt][0], ah[mt][1], ah[mt][2], ah[mt][3], a0);
                ldsm_x4(al[mt][0], al[mt][1], al[mt][2], al[mt][3], a0 + A_PL_B);
            }
            #pragma unroll
            for (int g = 0; g < NG; g++){
                uint32_t b0 = bad[g] + bS + (uint32_t)(ks*16*PNW*4);
                ldsm_x4_t(bh[2*g][0], bh[2*g][1], bh[2*g+1][0], bh[2*g+1][1], b0);
                ldsm_x4_t(bl[2*g][0], bl[2*g][1], bl[2*g+1][0], bl[2*g+1][1], b0 + B_PL*4);
            }
            #pragma unroll
            for (int mt = 0; mt < 2; mt++)
                #pragma unroll
                for (int nt = 0; nt < NF; nt++){
                    mma_bf16(acc[mt][nt], ah[mt], bh[nt]);
                    mma_bf16(acc[mt][nt], ah[mt], bl[nt]);
                    mma_bf16(acc[mt][nt], al[mt], bh[nt]);
                }
        }
    }

    #pragma unroll
    for (int mt = 0; mt < 2; mt++){
        int r0 = m0 + wm + mt*16 + lg;
        int r1 = r0 + 8;
        bool v0 = (mode == 0) || (r0 < cnt);
        bool v1 = (mode == 0) || (r1 < cnt);
        size_t cr0 = (size_t)((mode == 0) ? r0 : off + r0) * Nfull;
        size_t cr1 = (size_t)((mode == 0) ? r1 : off + r1) * Nfull;
        #pragma unroll
        for (int nt = 0; nt < NF; nt++){
            int col = n0 + wn + nt*8 + 2*lt;
            if (v0) *(float2*)(C + cr0 + col) = make_float2(acc[mt][nt][0], acc[mt][nt][1]);
            if (v1) *(float2*)(C + cr1 + col) = make_float2(acc[mt][nt][2], acc[mt][nt][3]);
        }
    }
}

// ---------------- fused gate_up + silu GEMM (BM=64, two 64-wide halves, 8 warps) ------
#define GPNW 36
#define GB_PL (32*GPNW)         // 1152 words per plane
#define GB_STG (4*GB_PL)        // hi_g, lo_g, hi_u, lo_u
__global__ void __launch_bounds__(256, 2) mma_gemm_silu(
    const float* __restrict__ A, const float* __restrict__ B, float* __restrict__ Cact,
    int Kd, int Nfull, long long BexpStride, int mode)
{
    const int halfN = Nfull >> 1;
    extern __shared__ __align__(16) uint32_t smemu[];
    uint32_t* As = smemu;                   // [2][A_STG]
    uint32_t* Bs = smemu + 2*A_STG;         // [2][GB_STG]
    const float** rowptr = (const float**)(smemu + 2*A_STG + 2*GB_STG);

    int tid = threadIdx.x, wid = tid >> 5, lane = tid & 31;
    int n0 = blockIdx.x * 64, m0 = blockIdx.y * 64;
    int cnt = 1 << 30, off = 0;
    const float* Bm = B;
    if (mode){
        int e = blockIdx.z;
        cnt = g_cnt[e]; if (cnt > CAP) cnt = CAP;
        if (m0 >= cnt) return;
        off = g_off[e];
        Bm = B + (size_t)e * (size_t)BexpStride;
    }
    if (tid < 64){
        int m = m0 + tid;
        const float* src;
        if (mode == 0)      src = A + (size_t)m * Kd;
        else if (m >= cnt)  src = A;
        else                src = A + (size_t)(g_perm[off + m] / KTOP) * Kd;
        rowptr[tid] = src;
    }
    __syncthreads();

    int arow = tid >> 2, aoff = (tid & 3) * 8;
    int k2l = tid >> 4, colg = tid & 15;
    int cb = colg * 4;
    const float* aptr = rowptr[arow] + aoff;
    const float* bg0 = Bm + (size_t)(2*k2l) * Nfull + n0 + cb;
    const float* bg1 = bg0 + Nfull;

    const int NK = Kd / BKT;
    float4 pa0, pa1, pg0, pg1, pu0, pu1;

    auto ldg = [&](int kt){
        size_t kc = (size_t)kt * BKT;
        pa0 = *(const float4*)(aptr + kc);
        pa1 = *(const float4*)(aptr + kc + 4);
        size_t bo = kc * Nfull;
        pg0 = *(const float4*)(bg0 + bo);
        pg1 = *(const float4*)(bg1 + bo);
        pu0 = *(const float4*)(bg0 + bo + halfN);
        pu1 = *(const float4*)(bg1 + bo + halfN);
    };

    auto sts = [&](int s){
        uint32_t h[4], l[4];
        split_pair(pa0.x, pa0.y, h[0], l[0]);
        split_pair(pa0.z, pa0.w, h[1], l[1]);
        split_pair(pa1.x, pa1.y, h[2], l[2]);
        split_pair(pa1.z, pa1.w, h[3], l[3]);
        uint32_t* ad = As + s*A_STG + arow*PKW + (aoff >> 1);
        *(uint4*)ad          = make_uint4(h[0], h[1], h[2], h[3]);
        *(uint4*)(ad + A_PL) = make_uint4(l[0], l[1], l[2], l[3]);

        uint32_t h0, h1, l0, l1;
        uint32_t* bd = Bs + s*GB_STG + (2*k2l)*GPNW + (cb >> 1);
        split_pair(pg0.x, pg0.y, h0, l0); split_pair(pg0.z, pg0.w, h1, l1);
        *(uint2*)bd           = make_uint2(h0, h1);
        *(uint2*)(bd + GB_PL) = make_uint2(l0, l1);
        split_pair(pg1.x, pg1.y, h0, l0); split_pair(pg1.z, pg1.w, h1, l1);
        *(uint2*)(bd + GPNW)          = make_uint2(h0, h1);
        *(uint2*)(bd + GPNW + GB_PL)  = make_uint2(l0, l1);
        bd += 2*GB_PL;
        split_pair(pu0.x, pu0.y, h0, l0); split_pair(pu0.z, pu0.w, h1, l1);
        *(uint2*)bd           = make_uint2(h0, h1);
        *(uint2*)(bd + GB_PL) = make_uint2(l0, l1);
        split_pair(pu1.x, pu1.y, h0, l0); split_pair(pu1.z, pu1.w, h1, l1);
        *(uint2*)(bd + GPNW)          = make_uint2(h0, h1);
        *(uint2*)(bd + GPNW + GB_PL)  = make_uint2(l0, l1);
    };

    float acc[2][2][2][4];   // [m][half][nt][v]
    #pragma unroll
    for (int i = 0; i < 2; i++)
        #pragma unroll
        for (int hh = 0; hh < 2; hh++)
            #pragma unroll
            for (int j = 0; j < 2; j++)
                #pragma unroll
                for (int v = 0; v < 4; v++) acc[i][hh][j][v] = 0.f;

    int wm = (wid >> 2) * 32, wn = (wid & 3) * 16;
    int lg = lane >> 2, lt = lane & 3;

    int lr = (lane & 7) + ((lane >> 3) & 1) * 8;
    int lk = (lane >> 4) * 8;
    uint32_t As_u = smem_u32(As), Bs_u = smem_u32(Bs);
    uint32_t aad[2];
    aad[0] = As_u + (uint32_t)(wm + lr) * 80u + (uint32_t)lk * 2u;
    aad[1] = aad[0] + 16u * 80u;
    uint32_t bad[2];
    #pragma unroll
    for (int hh = 0; hh < 2; hh++)
        bad[hh] = Bs_u + (uint32_t)(hh * 2 * GB_PL * 4) + (uint32_t)lr * (GPNW*4u) + (uint32_t)(wn + lk) * 2u;

    ldg(0);
    for (int kt = 0; kt < NK; kt++){
        int s = kt & 1;
        sts(s);
        __syncthreads();        // single barrier per iteration
        if (kt + 1 < NK) ldg(kt + 1);

        uint32_t aS = s ? (uint32_t)A_STG_B : 0u;
        uint32_t bS = s ? (uint32_t)(GB_STG*4) : 0u;
        #pragma unroll
        for (int ks = 0; ks < 2; ks++){
            uint32_t ah[2][4], al[2][4], bh[2][2][2], bl[2][2][2];
            #pragma unroll
            for (int mt = 0; mt < 2; mt++){
                uint32_t a0 = aad[mt] + aS + ks*32u;
                ldsm_x4(ah[mt][0], ah[mt][1], ah[mt][2], ah[mt][3], a0);
                ldsm_x4(al[mt][0], al[mt][1], al[mt][2], al[mt][3], a0 + A_PL_B);
            }
            #pragma unroll
            for (int hh = 0; hh < 2; hh++){
                uint32_t b0 = bad[hh] + bS + (uint32_t)(ks*16*GPNW*4);
                ldsm_x4_t(bh[hh][0][0], bh[hh][0][1], bh[hh][1][0], bh[hh][1][1], b0);
                ldsm_x4_t(bl[hh][0][0], bl[hh][0][1], bl[hh][1][0], bl[hh][1][1], b0 + GB_PL*4);
            }
            #pragma unroll
            for (int mt = 0; mt < 2; mt++)
                #pragma unroll
                for (int hh = 0; hh < 2; hh++)
                    #pragma unroll
                    for (int nt = 0; nt < 2; nt++){
                        mma_bf16(acc[mt][hh][nt], ah[mt], bh[hh][nt]);
                        mma_bf16(acc[mt][hh][nt], ah[mt], bl[hh][nt]);
                        mma_bf16(acc[mt][hh][nt], al[mt], bh[hh][nt]);
                    }
        }
    }

    #pragma unroll
    for (int mt = 0; mt < 2; mt++){
        int r0 = m0 + wm + mt*16 + lg;
        int r1 = r0 + 8;
        bool v0 = (mode == 0) || (r0 < cnt);
        bool v1 = (mode == 0) || (r1 < cnt);
        size_t cr0 = (size_t)((mode == 0) ? r0 : off + r0) * halfN;
        size_t cr1 = (size_t)((mode == 0) ? r1 : off + r1) * halfN;
        #pragma unroll
        for (int nt = 0; nt < 2; nt++){
            int col = n0 + wn + nt*8 + 2*lt;
            if (v0){
                float2 o = make_float2(silu_mul(acc[mt][0][nt][0], acc[mt][1][nt][0]),
                                       silu_mul(acc[mt][0][nt][1], acc[mt][1][nt][1]));
                *(float2*)(Cact + cr0 + col) = o;
            }
            if (v1){
                float2 o = make_float2(silu_mul(acc[mt][0][nt][2], acc[mt][1][nt][2]),
                                       silu_mul(acc[mt][0][nt][3], acc[mt][1][nt][3]));
                *(float2*)(Cact + cr1 + col) = o;
            }
        }
    }
}

// ---------------- router: 8 tokens per block ----------------
__global__ __launch_bounds__(256) void router_topk(
    const float* __restrict__ x, const float* __restrict__ gw, const float* __restrict__ bias)
{
    __shared__ float xs[8][H];
    __shared__ float part[4][8][64];
    __shared__ float sc[8][64], sbb[8][64];
    int t0 = blockIdx.x * 8;
    for (int i = threadIdx.x; i < 8 * (H/4); i += 256){
        int tk = i / (H/4), j = i % (H/4);
        ((float4*)xs[tk])[j] = ((const float4*)(x + (size_t)(t0 + tk) * H))[j];
    }
    __syncthreads();
    int c = threadIdx.x >> 6, e = threadIdx.x & 63;
    float acc[8];
    #pragma unroll
    for (int tk = 0; tk < 8; tk++) acc[tk] = 0.f;
    const float* w = gw + (size_t)c * 256 * 64 + e;
    for (int h = 0; h < 256; h++){
        float wv = w[(size_t)h * 64];
        float* xcol = &xs[0][c * 256 + h];
        #pragma unroll
        for (int tk = 0; tk < 8; tk++) acc[tk] += xcol[tk * H] * wv;
    }
    #pragma unroll
    for (int tk = 0; tk < 8; tk++) part[c][tk][e] = acc[tk];
    __syncthreads();
    for (int i = threadIdx.x; i < 512; i += 256){
        int tk = i >> 6, ee = i & 63;
        float l = part[0][tk][ee] + part[1][tk][ee] + part[2][tk][ee] + part[3][tk][ee];
        float s = 1.f / (1.f + expf(-l));
        sc[tk][ee] = s; sbb[tk][ee] = s + bias[ee];
    }
    __syncthreads();
    if (threadIdx.x < 8){
        int tk = threadIdx.x;
        int t = t0 + tk;
        float gs[NGRP];
        #pragma unroll
        for (int g = 0; g < NGRP; g++){
            float m1 = -1e30f, m2 = -1e30f;
            #pragma unroll
            for (int j = 0; j < 8; j++){
                float v = sbb[tk][g * 8 + j];
                if (v > m1){ m2 = m1; m1 = v; } else if (v > m2){ m2 = v; }
            }
            gs[g] = m1 + m2;
        }
        unsigned gsel = 0;
        #pragma unroll
        for (int it = 0; it < TKG; it++){
            float best = -1e30f; int bi = 0;
            for (int g = 0; g < NGRP; g++)
                if (!((gsel >> g) & 1) && gs[g] > best){ best = gs[g]; bi = g; }
            gsel |= 1u << bi;
        }
        unsigned long long used = 0; float wsum = 0.f;
        float wk[KTOP]; int ek[KTOP];
        #pragma unroll
        for (int it = 0; it < KTOP; it++){
            float best = -1e30f; int bi = 0;
            for (int ee = 0; ee < 64; ee++){
                if (((gsel >> (ee >> 3)) & 1) && !((used >> ee) & 1) && sbb[tk][ee] > best){
                    best = sbb[tk][ee]; bi = ee;
                }
            }
            used |= 1ull << bi;
            ek[it] = bi; wk[it] = sc[tk][bi]; wsum += sc[tk][bi];
        }
        float inv = 1.f / wsum;
        #pragma unroll
        for (int k = 0; k < KTOP; k++){
            g_eidx[t * KTOP + k] = ek[k];
            g_w[t * KTOP + k] = wk[k] * inv;
        }
    }
}

// ---------------- fused dispatch (all in shared memory) ----------------
#define DISP_PER (A_TOT/1024)   // 6 assignments per thread
__global__ __launch_bounds__(1024) void dispatch_k()
{
    __shared__ int scnt[E];
    __shared__ int soff[E+1];
    int tid = threadIdx.x;
    if (tid < E) scnt[tid] = 0;
    __syncthreads();
    int eloc[DISP_PER], sloc[DISP_PER];
    #pragma unroll
    for (int j = 0; j < DISP_PER; j++){
        int a = tid + j * 1024;
        int e = g_eidx[a];
        eloc[j] = e;
        sloc[j] = atomicAdd(&scnt[e], 1);
    }
    __syncthreads();
    if (tid == 0){
        int s = 0;
        #pragma unroll
        for (int e = 0; e < E; e++){
            soff[e] = s;
            int c = scnt[e];
            s += (c > CAP) ? CAP : c;
        }
        soff[E] = s;
    }
    __syncthreads();
    if (tid < E){ g_cnt[tid] = scnt[tid]; g_off[tid] = soff[tid]; }
    if (tid == 0) g_off[E] = soff[E];
    #pragma unroll
    for (int j = 0; j < DISP_PER; j++){
        int a = tid + j * 1024;
        int sl = sloc[j];
        if (sl < CAP){
            int r = soff[eloc[j]] + sl;
            g_perm[r] = a;
            g_rowpos[a] = r;
        } else {
            g_rowpos[a] = -1;
        }
    }
}

// ---------------- combine ----------------
__global__ __launch_bounds__(256) void combine_k(float* __restrict__ out)
{
    int t = blockIdx.x;
    int h0 = threadIdx.x * 4;
    float4 acc = *(float4*)&out[(size_t)t * H + h0];
    #pragma unroll
    for (int k = 0; k < KTOP; k++){
        int a = t * KTOP + k;
        int r = g_rowpos[a];
        if (r >= 0){
            float w = 2.5f * g_w[a];
            float4 y = *(const float4*)&g_y[(size_t)r * H + h0];
            acc.x += w * y.x; acc.y += w * y.y; acc.z += w * y.z; acc.w += w * y.w;
        }
    }
    *(float4*)&out[(size_t)t * H + h0] = acc;
}

// ---------------- launch ----------------
extern "C" void kernel_launch(void* const* d_in, const int* in_sizes, int n_in,
                              void* d_out, int out_size)
{
    const float* x      = (const float*)d_in[0];
    const float* gate_w = (const float*)d_in[1];
    const float* e_bias = (const float*)d_in[2];
    const float* w_gu   = (const float*)d_in[3];
    const float* w_dn   = (const float*)d_in[4];
    const float* ws_gu  = (const float*)d_in[5];
    const float* ws_dn  = (const float*)d_in[6];
    float* out = (float*)d_out;

    float *p_actS, *p_act, *p_y;
    cudaGetSymbolAddress((void**)&p_actS, g_actS);
    cudaGetSymbolAddress((void**)&p_act,  g_act);
    cudaGetSymbolAddress((void**)&p_y,    g_y);

    const int SMEM_DN128 = (2*A_STG + 2*2*(32*68))*4 + 64*8;
    const int SMEM_DN64  = (2*A_STG + 2*2*(32*36))*4 + 64*8;
    const int SMEM_GU    = (2*A_STG + 2*GB_STG)*4 + 64*8;
    cudaFuncSetAttribute(mma_gemm<128>, cudaFuncAttributeMaxDynamicSharedMemorySize, SMEM_DN128);
    cudaFuncSetAttribute(mma_gemm<64>,  cudaFuncAttributeMaxDynamicSharedMemorySize, SMEM_DN64);
    cudaFuncSetAttribute(mma_gemm_silu, cudaFuncAttributeMaxDynamicSharedMemorySize, SMEM_GU);

    // fork a second stream for the shared-expert chain (independent of routing)
    cudaStream_t s1;
    cudaStreamCreateWithFlags(&s1, cudaStreamNonBlocking);
    cudaEvent_t evFork, evJoin;
    cudaEventCreateWithFlags(&evFork, cudaEventDisableTiming);
    cudaEventCreateWithFlags(&evJoin, cudaEventDisableTiming);
    cudaEventRecord(evFork, 0);
    cudaStreamWaitEvent(s1, evFork, 0);

    // stream s1: shared experts (gu+silu -> actS, down -> out)
    mma_gemm_silu<<<dim3(NSH_HALF / 64, T / 64, 1), 256, SMEM_GU, s1>>>(
        x, ws_gu, p_actS, H, NSH_2, 0, 0);
    mma_gemm<64><<<dim3(H / 64, T / 64, 1), 256, SMEM_DN64, s1>>>(
        p_actS, ws_dn, out, NSH_HALF, H, 0, 0);
    cudaEventRecord(evJoin, s1);

    // stream 0: router + dispatch + routed experts
    router_topk<<<T/8, 256>>>(x, gate_w, e_bias);
    dispatch_k<<<1, 1024>>>();
    mma_gemm_silu<<<dim3(ISZ / 64, CAP / 64, E), 256, SMEM_GU>>>(
        x, w_gu, p_act, H, TWO_I, (long long)H * TWO_I, 1);
    mma_gemm<128><<<dim3(H / 128, CAP / 64, E), 256, SMEM_DN128>>>(
        p_act, w_dn, p_y, ISZ, H, (long long)ISZ * H, 2);

    // join: combine (reads out written by dn_shared on s1, and g_y from stream 0)
    cudaStreamWaitEvent(0, evJoin, 0);
    combine_k<<<T, 256>>>(out);

    cudaEventDestroy(evFork);
    cudaEventDestroy(evJoin);
    cudaStreamDestroy(s1);
}